// round 12
// baseline (speedup 1.0000x reference)
#include <cuda_runtime.h>
#include <cuda_bf16.h>
#include <mma.h>
#include <math.h>

using namespace nvcuda;

// Problem constants
#define NTOK   2304     // 48*48 tokens
#define CDIM   256      // d_model
#define EDIM   512      // 2*d_model
#define HEADS  8
#define VHEADS 16       // heads * 2 softmax halves
#define DH     32       // per-half head dim
#define DV     64       // value dim per head

#define PADB 40         // Q/K bf16 smem row pitch (elements)
#define PADS 72         // S/V fp32 smem row pitch (floats)
// attn dynamic smem bytes:
//   Qhi/Qlo/Khi/Klo 4*(64*40*2) + Vs/Ss 2*(64*72*4) + Ones 8*16*4 + Lsm 64*16*4
#define ATTN_SMEM_BYTES (4*64*PADB*2 + 2*64*PADS*4 + 8*16*4 + 64*16*4)  // 60.5 KB

// ---------------------------------------------------------------------------
// Scratch (device globals)
// ---------------------------------------------------------------------------
__device__ float g_q[HEADS * NTOK * 64];
__device__ float g_k[HEADS * NTOK * 64];
__device__ float g_v[HEADS * NTOK * 64];
__device__ float g_o[VHEADS * NTOK * 64];
__device__ float g_oc[NTOK * EDIM];
__device__ float g_lam[HEADS];

// tf32 fragments (PV path)
typedef wmma::fragment<wmma::matrix_a, 16, 16, 8, wmma::precision::tf32, wmma::row_major> FragA;
typedef wmma::fragment<wmma::matrix_b, 16, 16, 8, wmma::precision::tf32, wmma::row_major> FragBr;
typedef wmma::fragment<wmma::accumulator, 16, 16, 8, float> FragC;

// bf16 fragments
typedef wmma::fragment<wmma::matrix_a, 16, 16, 16, __nv_bfloat16, wmma::row_major> HFragA;
typedef wmma::fragment<wmma::matrix_a, 16, 16, 16, __nv_bfloat16, wmma::col_major> HFragAc;
typedef wmma::fragment<wmma::matrix_b, 16, 16, 16, __nv_bfloat16, wmma::col_major> HFragBc;
typedef wmma::fragment<wmma::accumulator, 16, 16, 16, float> HFragC;

__device__ __forceinline__ void bf16_split(float f, __nv_bfloat16& hi, __nv_bfloat16& lo)
{
    hi = __float2bfloat16_rn(f);
    lo = __float2bfloat16_rn(f - __bfloat162float(hi));
}

// ---------------------------------------------------------------------------
// QKV projection, bf16 hi/lo-split 3-term wmma (R10 winner — unchanged).
// Y[n][e] = sum_c X[c*NTOK+n] * W[e*256+c]
// grid (36, 8, 3), 128 threads.
// ---------------------------------------------------------------------------
__global__ __launch_bounds__(128) void proj_tc_kernel(
    const float* __restrict__ X,
    const float* __restrict__ Wq,
    const float* __restrict__ Wk,
    const float* __restrict__ Wv)
{
    const int sel = blockIdx.z;
    const float* __restrict__ W = (sel == 0) ? Wq : (sel == 1) ? Wk : Wv;
    float* __restrict__ Y = (sel == 0) ? g_q : (sel == 1) ? g_k : g_v;

    __shared__ __nv_bfloat16 Xh[32 * 72], Xl[32 * 72];   // [c][n], n contiguous
    __shared__ __nv_bfloat16 Wh[64 * PADB], Wl[64 * PADB]; // [e][c], c contiguous

    const int tid = threadIdx.x;
    const int wid = tid >> 5;
    const int n0 = blockIdx.x * 64;
    const int hI = blockIdx.y;

    HFragC o[4];
    #pragma unroll
    for (int nt = 0; nt < 4; nt++) wmma::fill_fragment(o[nt], 0.0f);

    for (int c0 = 0; c0 < CDIM; c0 += 32) {
        __syncthreads();
        #pragma unroll
        for (int i = 0; i < 16; i++) {
            const int idx = tid + i * 128;
            const int c = idx >> 6, nl = idx & 63;
            bf16_split(X[(size_t)(c0 + c) * NTOK + n0 + nl],
                       Xh[c * 72 + nl], Xl[c * 72 + nl]);
        }
        #pragma unroll
        for (int i = 0; i < 16; i++) {
            const int idx = tid + i * 128;
            const int e = idx >> 5, cl = idx & 31;
            bf16_split(W[(size_t)(hI * 64 + e) * CDIM + c0 + cl],
                       Wh[e * PADB + cl], Wl[e * PADB + cl]);
        }
        __syncthreads();

        #pragma unroll
        for (int kt = 0; kt < 2; kt++) {
            HFragAc ah, al;
            wmma::load_matrix_sync(ah, Xh + (kt * 16) * 72 + wid * 16, 72);
            wmma::load_matrix_sync(al, Xl + (kt * 16) * 72 + wid * 16, 72);
            #pragma unroll
            for (int nt = 0; nt < 4; nt++) {
                HFragBc bh, bl;
                wmma::load_matrix_sync(bh, Wh + (nt * 16) * PADB + kt * 16, PADB);
                wmma::load_matrix_sync(bl, Wl + (nt * 16) * PADB + kt * 16, PADB);
                wmma::mma_sync(o[nt], ah, bh, o[nt]);
                wmma::mma_sync(o[nt], ah, bl, o[nt]);
                wmma::mma_sync(o[nt], al, bh, o[nt]);
            }
        }
    }

    float* Yb = Y + (size_t)hI * NTOK * 64;
    #pragma unroll
    for (int nt = 0; nt < 4; nt++)
        wmma::store_matrix_sync(Yb + (size_t)(n0 + wid * 16) * 64 + nt * 16,
                                o[nt], 64, wmma::mem_row_major);
}

// ---------------------------------------------------------------------------
// lambda[h]
// ---------------------------------------------------------------------------
__global__ void lam_kernel(const float* __restrict__ lq1, const float* __restrict__ lk1,
                           const float* __restrict__ lq2, const float* __restrict__ lk2)
{
    const int h = threadIdx.x >> 5, lane = threadIdx.x & 31;
    float p1 = lq1[h * DH + lane] * lk1[h * DH + lane];
    float p2 = lq2[h * DH + lane] * lk2[h * DH + lane];
    #pragma unroll
    for (int off = 16; off; off >>= 1) {
        p1 += __shfl_xor_sync(0xffffffffu, p1, off);
        p2 += __shfl_xor_sync(0xffffffffu, p2, off);
    }
    if (lane == 0) g_lam[h] = expf(p1) - expf(p2) + 0.8f;
}

// ---------------------------------------------------------------------------
// Tensor-core flash attention v3: BM=64 x BN=64, 128 threads, 4 warps.
// QK^T: bf16 hi/lo split (R9/R10 path). PV: tf32 pre-rounded.
// NEW vs R10:
//  - Off-diagonal tiles: exp + tf32-round applied IN REGISTERS on the S
//    accumulator fragments (uniform elementwise — legal on wmma frags),
//    P stored into the warp's OWN 16-row Ss strip -> only __syncwarp needed.
//    Per tile: 4 __syncthreads -> 2, S smem round-trip eliminated.
//  - Row sums l computed by an extra MMA per kt against a constant
//    ones-column B fragment (l = P · [1,0..0]), using the SAME smem P as
//    O -> normalization exactly consistent. No scalar lrow bookkeeping.
//  - Diagonal tile (needs causal mask coordinates) keeps the smem exp path.
// Pair folding: qb = bx and 35-bx. grid (18, 16), 60.5KB smem, 3 CTAs/SM.
// ---------------------------------------------------------------------------
__global__ __launch_bounds__(128) void attn_tc_kernel()
{
    extern __shared__ float sm[];
    __nv_bfloat16* Qhi = (__nv_bfloat16*)sm;         // [64][PADB]
    __nv_bfloat16* Qlo = Qhi + 64 * PADB;            // [64][PADB]
    __nv_bfloat16* Khi = Qlo + 64 * PADB;            // [64][PADB]
    __nv_bfloat16* Klo = Khi + 64 * PADB;            // [64][PADB]
    float* Vs   = (float*)(Klo + 64 * PADB);         // [64][PADS] tf32-rounded
    float* Ss   = Vs + 64 * PADS;                    // [64][PADS] S / P / O
    float* Ones = Ss + 64 * PADS;                    // [8][16] col0 = 1
    float* Lsm  = Ones + 8 * 16;                     // [64][16] row sums

    const int vh   = blockIdx.y;
    const int h    = vh >> 1;
    const int half = vh & 1;

    const float* __restrict__ Qp = g_q + (size_t)h * NTOK * 64 + half * DH;
    const float* __restrict__ Kp = g_k + (size_t)h * NTOK * 64 + half * DH;
    const float* __restrict__ Vp = g_v + (size_t)h * NTOK * 64;
    float* __restrict__ Op       = g_o + (size_t)vh * NTOK * 64;

    const int tid = threadIdx.x;
    const int wid = tid >> 5;              // 0..3, 16-row q strip

    const float scale = 0.17677669529663687f;  // 1/sqrt(32)

    // Init ones tile (8 rows x 16 cols, col 0 = 1) — constant for whole kernel
    if (tid < 128) {
        // 8*16 = 128 entries
        Ones[tid] = ((tid & 15) == 0) ? 1.0f : 0.0f;
    }
    __syncthreads();

    FragBr onesfrag;                       // persistent across tiles/passes
    wmma::load_matrix_sync(onesfrag, Ones, 16);

    #pragma unroll 1
    for (int pass = 0; pass < 2; pass++) {
        const int qb = (pass == 0) ? (int)blockIdx.x : 35 - (int)blockIdx.x;
        const int n0 = qb * 64;

        __syncthreads();   // previous pass fully done with smem

        // Stage Q (scaled) split into bf16 hi/lo: 64 x 32
        #pragma unroll
        for (int i = 0; i < 16; i++) {
            const int idx = tid + i * 128;
            const int r = idx >> 5, d = idx & 31;
            const float f = Qp[(size_t)(n0 + r) * 64 + d] * scale;
            bf16_split(f, Qhi[r * PADB + d], Qlo[r * PADB + d]);
        }
        __syncthreads();

        // Per-warp Q fragments (row-major, k16), loaded once per pass
        HFragA qh[2], ql[2];
        #pragma unroll
        for (int kt = 0; kt < 2; kt++) {
            wmma::load_matrix_sync(qh[kt], Qhi + (wid * 16) * PADB + kt * 16, PADB);
            wmma::load_matrix_sync(ql[kt], Qlo + (wid * 16) * PADB + kt * 16, PADB);
        }

        FragC o_acc[4], l_acc;
        #pragma unroll
        for (int nt = 0; nt < 4; nt++) wmma::fill_fragment(o_acc[nt], 0.0f);
        wmma::fill_fragment(l_acc, 0.0f);

        const int kb_max = qb;
        for (int kb = 0; kb <= kb_max; kb++) {
            const int k0 = kb << 6;
            __syncthreads();   // previous tile's MMAs done reading Khi/Klo/Vs

            // Stage K 64x32, split bf16 hi/lo
            #pragma unroll
            for (int i = 0; i < 16; i++) {
                const int idx = tid + i * 128;
                const int r = idx >> 5, d = idx & 31;
                bf16_split(Kp[(size_t)(k0 + r) * 64 + d],
                           Khi[r * PADB + d], Klo[r * PADB + d]);
            }
            // Stage V 64x64, pre-rounded to tf32
            #pragma unroll
            for (int i = 0; i < 8; i++) {
                const int idx = tid + i * 128;
                const int r = idx >> 4, c4 = (idx & 15) * 4;
                float4 f = *(const float4*)&Vp[(size_t)(k0 + r) * 64 + c4];
                f.x = wmma::__float_to_tf32(f.x);
                f.y = wmma::__float_to_tf32(f.y);
                f.z = wmma::__float_to_tf32(f.z);
                f.w = wmma::__float_to_tf32(f.w);
                *(float4*)&Vs[r * PADS + c4] = f;
            }
            __syncthreads();

            // S = Q K^T via bf16 split: qh*kh + qh*kl + ql*kh
            HFragC s_acc[4];
            #pragma unroll
            for (int nt = 0; nt < 4; nt++) wmma::fill_fragment(s_acc[nt], 0.0f);
            #pragma unroll
            for (int kt = 0; kt < 2; kt++) {
                #pragma unroll
                for (int nt = 0; nt < 4; nt++) {
                    HFragBc kh, kl;
                    wmma::load_matrix_sync(kh, Khi + (nt * 16) * PADB + kt * 16, PADB);
                    wmma::load_matrix_sync(kl, Klo + (nt * 16) * PADB + kt * 16, PADB);
                    wmma::mma_sync(s_acc[nt], qh[kt], kh, s_acc[nt]);
                    wmma::mma_sync(s_acc[nt], qh[kt], kl, s_acc[nt]);
                    wmma::mma_sync(s_acc[nt], ql[kt], kh, s_acc[nt]);
                }
            }

            if (kb != kb_max) {
                // Fast path: exp + tf32-round in registers (uniform elementwise),
                // store P into this warp's OWN strip -> warp-local only.
                #pragma unroll
                for (int nt = 0; nt < 4; nt++) {
                    #pragma unroll
                    for (int i = 0; i < 8; i++)
                        s_acc[nt].x[i] = wmma::__float_to_tf32(__expf(s_acc[nt].x[i]));
                    wmma::store_matrix_sync(Ss + (wid * 16) * PADS + nt * 16,
                                            s_acc[nt], PADS, wmma::mem_row_major);
                }
                __syncwarp();
            } else {
                // Diagonal tile: causal mask needs coordinates -> smem path
                #pragma unroll
                for (int nt = 0; nt < 4; nt++)
                    wmma::store_matrix_sync(Ss + (wid * 16) * PADS + nt * 16,
                                            s_acc[nt], PADS, wmma::mem_row_major);
                __syncthreads();
                {
                    const int r  = tid & 63;
                    const int co = (tid >> 6) * 32;
                    float* row = Ss + r * PADS + co;
                    const int lim = n0 + r - k0 - co;   // valid while col <= lim
                    #pragma unroll
                    for (int i = 0; i < 8; i++) {
                        float4 f = *(float4*)&row[i * 4];
                        const int c = i * 4;
                        f.x = (c + 0 <= lim) ? wmma::__float_to_tf32(__expf(f.x)) : 0.0f;
                        f.y = (c + 1 <= lim) ? wmma::__float_to_tf32(__expf(f.y)) : 0.0f;
                        f.z = (c + 2 <= lim) ? wmma::__float_to_tf32(__expf(f.z)) : 0.0f;
                        f.w = (c + 3 <= lim) ? wmma::__float_to_tf32(__expf(f.w)) : 0.0f;
                        *(float4*)&row[i * 4] = f;
                    }
                }
                __syncthreads();
            }

            // O += P @ V ; l += P @ ones  (tf32, pure mma; same smem P for both)
            #pragma unroll
            for (int kt = 0; kt < 8; kt++) {
                FragA a;
                wmma::load_matrix_sync(a, Ss + (wid * 16) * PADS + kt * 8, PADS);
                wmma::mma_sync(l_acc, a, onesfrag, l_acc);
                #pragma unroll
                for (int nt = 0; nt < 4; nt++) {
                    FragBr vb;
                    wmma::load_matrix_sync(vb, Vs + (kt * 8) * PADS + nt * 16, PADS);
                    wmma::mma_sync(o_acc[nt], a, vb, o_acc[nt]);
                }
            }
        }

        // Epilogue: O frags + l frag -> smem, normalize, store
        wmma::store_matrix_sync(Lsm + (wid * 16) * 16, l_acc, 16, wmma::mem_row_major);
        #pragma unroll
        for (int nt = 0; nt < 4; nt++)
            wmma::store_matrix_sync(Ss + (wid * 16) * PADS + nt * 16, o_acc[nt],
                                    PADS, wmma::mem_row_major);
        __syncthreads();
        {
            const int r  = tid & 63;
            const int co = (tid >> 6) * 32;
            const float inv = 1.0f / Lsm[r * 16];
            const float* row = Ss + r * PADS + co;
            float* dst = Op + (size_t)(n0 + r) * 64 + co;
            #pragma unroll
            for (int i = 0; i < 8; i++) {
                float4 f = *(const float4*)&row[i * 4];
                f.x *= inv; f.y *= inv; f.z *= inv; f.w *= inv;
                *(float4*)&dst[i * 4] = f;
            }
        }
    }
}

// ---------------------------------------------------------------------------
// Combine halves + RMS norm
// ---------------------------------------------------------------------------
__global__ __launch_bounds__(256) void combine_kernel(const float* __restrict__ rms_scale)
{
    const int n = blockIdx.x;
    const int h = threadIdx.x >> 5, lane = threadIdx.x & 31;
    const float lam = g_lam[h];

    const float* o1 = g_o + ((size_t)(2 * h) * NTOK + n) * 64;
    const float* o2 = g_o + ((size_t)(2 * h + 1) * NTOK + n) * 64;

    const float a = o1[lane]      - lam * o2[lane];
    const float b = o1[lane + 32] - lam * o2[lane + 32];

    float ss = a * a + b * b;
    #pragma unroll
    for (int off = 16; off; off >>= 1)
        ss += __shfl_xor_sync(0xffffffffu, ss, off);

    const float inv = rsqrtf(ss * (1.0f / 64.0f) + 1e-5f) * 0.2f;

    float* out = g_oc + (size_t)n * EDIM + h * 64;
    out[lane]      = a * inv * rms_scale[lane];
    out[lane + 32] = b * inv * rms_scale[lane + 32];
}

// ---------------------------------------------------------------------------
// Output projection, bf16 hi/lo-split 3-term wmma (R10 winner — unchanged).
// grid (36, 4), 128 threads.
// ---------------------------------------------------------------------------
__global__ __launch_bounds__(128) void out_tc_kernel(
    const float* __restrict__ Wo, float* __restrict__ out)
{
    __shared__ __nv_bfloat16 Ah[64 * PADB], Al[64 * PADB];  // Wo [c][e], e contiguous
    __shared__ __nv_bfloat16 Bh[64 * PADB], Bl[64 * PADB];  // oc [n][e], e contiguous

    const int tid = threadIdx.x;
    const int wid = tid >> 5;
    const int n0 = blockIdx.x * 64, c0 = blockIdx.y * 64;

    HFragC o[4];
    #pragma unroll
    for (int nt = 0; nt < 4; nt++) wmma::fill_fragment(o[nt], 0.0f);

    for (int e0 = 0; e0 < EDIM; e0 += 32) {
        __syncthreads();
        #pragma unroll
        for (int i = 0; i < 16; i++) {
            const int idx = tid + i * 128;
            const int cc = idx >> 5, el = idx & 31;
            bf16_split(Wo[(size_t)(c0 + cc) * EDIM + e0 + el],
                       Ah[cc * PADB + el], Al[cc * PADB + el]);
        }
        #pragma unroll
        for (int i = 0; i < 16; i++) {
            const int idx = tid + i * 128;
            const int nn = idx >> 5, el = idx & 31;
            bf16_split(g_oc[(size_t)(n0 + nn) * EDIM + e0 + el],
                       Bh[nn * PADB + el], Bl[nn * PADB + el]);
        }
        __syncthreads();

        #pragma unroll
        for (int kt = 0; kt < 2; kt++) {
            HFragA ah, al;   // (c, e) row-major
            wmma::load_matrix_sync(ah, Ah + (wid * 16) * PADB + kt * 16, PADB);
            wmma::load_matrix_sync(al, Al + (wid * 16) * PADB + kt * 16, PADB);
            #pragma unroll
            for (int nt = 0; nt < 4; nt++) {
                HFragBc bh, bl;  // (e, n) col-major view of oc[n][e]
                wmma::load_matrix_sync(bh, Bh + (nt * 16) * PADB + kt * 16, PADB);
                wmma::load_matrix_sync(bl, Bl + (nt * 16) * PADB + kt * 16, PADB);
                wmma::mma_sync(o[nt], ah, bh, o[nt]);
                wmma::mma_sync(o[nt], ah, bl, o[nt]);
                wmma::mma_sync(o[nt], al, bh, o[nt]);
            }
        }
    }

    #pragma unroll
    for (int nt = 0; nt < 4; nt++)
        wmma::store_matrix_sync(out + (size_t)(c0 + wid * 16) * NTOK + n0 + nt * 16,
                                o[nt], NTOK, wmma::mem_row_major);
}

// ---------------------------------------------------------------------------
// Launch
// ---------------------------------------------------------------------------
extern "C" void kernel_launch(void* const* d_in, const int* in_sizes, int n_in,
                              void* d_out, int out_size)
{
    const float* X   = (const float*)d_in[0];
    const float* Wq  = (const float*)d_in[1];
    const float* Wk  = (const float*)d_in[2];
    const float* Wv  = (const float*)d_in[3];
    const float* Wo  = (const float*)d_in[4];
    const float* lq1 = (const float*)d_in[5];
    const float* lk1 = (const float*)d_in[6];
    const float* lq2 = (const float*)d_in[7];
    const float* lk2 = (const float*)d_in[8];
    const float* rs  = (const float*)d_in[9];
    float* out = (float*)d_out;

    static bool attr_set = false;
    if (!attr_set) {
        cudaFuncSetAttribute(attn_tc_kernel,
                             cudaFuncAttributeMaxDynamicSharedMemorySize,
                             ATTN_SMEM_BYTES);
        attr_set = true;
    }

    proj_tc_kernel<<<dim3(NTOK / 64, EDIM / 64, 3), 128>>>(X, Wq, Wk, Wv);
    lam_kernel<<<1, 256>>>(lq1, lk1, lq2, lk2);
    attn_tc_kernel<<<dim3(18, VHEADS), 128, ATTN_SMEM_BYTES>>>();
    combine_kernel<<<NTOK, 256>>>(rs);
    out_tc_kernel<<<dim3(NTOK / 64, CDIM / 64), 128>>>(Wo, out);
}

// round 13
// speedup vs baseline: 1.0247x; 1.0247x over previous
#include <cuda_runtime.h>
#include <cuda_bf16.h>
#include <mma.h>
#include <math.h>

using namespace nvcuda;

// Problem constants
#define NTOK   2304     // 48*48 tokens
#define CDIM   256      // d_model
#define EDIM   512      // 2*d_model
#define HEADS  8
#define VHEADS 16       // heads * 2 softmax halves
#define DH     32       // per-half head dim
#define DV     64       // value dim per head

#define PADB 40         // Q/K bf16 smem row pitch (elements)
#define PADS 72         // S/V fp32 smem row pitch (floats)
// attn dynamic smem bytes:
//   Qhi/Qlo/Khi/Klo 4*(64*40*2) + Vs/Ss 2*(64*72*4) + Ls 128*4
#define ATTN_SMEM_BYTES (4*64*PADB*2 + 2*64*PADS*4 + 128*4)  // 56.5 KB -> 3 CTAs/SM

// ---------------------------------------------------------------------------
// Scratch (device globals)
// ---------------------------------------------------------------------------
__device__ float g_q[HEADS * NTOK * 64];
__device__ float g_k[HEADS * NTOK * 64];
__device__ float g_v[HEADS * NTOK * 64];
__device__ float g_o[VHEADS * NTOK * 64];
__device__ float g_oc[NTOK * EDIM];
__device__ float g_lam[HEADS];

// tf32 fragments (PV path)
typedef wmma::fragment<wmma::matrix_a, 16, 16, 8, wmma::precision::tf32, wmma::row_major> FragA;
typedef wmma::fragment<wmma::matrix_b, 16, 16, 8, wmma::precision::tf32, wmma::row_major> FragBr;
typedef wmma::fragment<wmma::accumulator, 16, 16, 8, float> FragC;

// bf16 fragments
typedef wmma::fragment<wmma::matrix_a, 16, 16, 16, __nv_bfloat16, wmma::row_major> HFragA;
typedef wmma::fragment<wmma::matrix_a, 16, 16, 16, __nv_bfloat16, wmma::col_major> HFragAc;
typedef wmma::fragment<wmma::matrix_b, 16, 16, 16, __nv_bfloat16, wmma::col_major> HFragBc;
typedef wmma::fragment<wmma::accumulator, 16, 16, 16, float> HFragC;

__device__ __forceinline__ void bf16_split(float f, __nv_bfloat16& hi, __nv_bfloat16& lo)
{
    hi = __float2bfloat16_rn(f);
    lo = __float2bfloat16_rn(f - __bfloat162float(hi));
}

// ---------------------------------------------------------------------------
// QKV projection, bf16 hi/lo-split 3-term wmma (R10 winner — unchanged).
// Y[n][e] = sum_c X[c*NTOK+n] * W[e*256+c]
// grid (36, 8, 3), 128 threads.
// ---------------------------------------------------------------------------
__global__ __launch_bounds__(128) void proj_tc_kernel(
    const float* __restrict__ X,
    const float* __restrict__ Wq,
    const float* __restrict__ Wk,
    const float* __restrict__ Wv)
{
    const int sel = blockIdx.z;
    const float* __restrict__ W = (sel == 0) ? Wq : (sel == 1) ? Wk : Wv;
    float* __restrict__ Y = (sel == 0) ? g_q : (sel == 1) ? g_k : g_v;

    __shared__ __nv_bfloat16 Xh[32 * 72], Xl[32 * 72];   // [c][n], n contiguous
    __shared__ __nv_bfloat16 Wh[64 * PADB], Wl[64 * PADB]; // [e][c], c contiguous

    const int tid = threadIdx.x;
    const int wid = tid >> 5;
    const int n0 = blockIdx.x * 64;
    const int hI = blockIdx.y;

    HFragC o[4];
    #pragma unroll
    for (int nt = 0; nt < 4; nt++) wmma::fill_fragment(o[nt], 0.0f);

    for (int c0 = 0; c0 < CDIM; c0 += 32) {
        __syncthreads();
        #pragma unroll
        for (int i = 0; i < 16; i++) {
            const int idx = tid + i * 128;
            const int c = idx >> 6, nl = idx & 63;
            bf16_split(X[(size_t)(c0 + c) * NTOK + n0 + nl],
                       Xh[c * 72 + nl], Xl[c * 72 + nl]);
        }
        #pragma unroll
        for (int i = 0; i < 16; i++) {
            const int idx = tid + i * 128;
            const int e = idx >> 5, cl = idx & 31;
            bf16_split(W[(size_t)(hI * 64 + e) * CDIM + c0 + cl],
                       Wh[e * PADB + cl], Wl[e * PADB + cl]);
        }
        __syncthreads();

        #pragma unroll
        for (int kt = 0; kt < 2; kt++) {
            HFragAc ah, al;
            wmma::load_matrix_sync(ah, Xh + (kt * 16) * 72 + wid * 16, 72);
            wmma::load_matrix_sync(al, Xl + (kt * 16) * 72 + wid * 16, 72);
            #pragma unroll
            for (int nt = 0; nt < 4; nt++) {
                HFragBc bh, bl;
                wmma::load_matrix_sync(bh, Wh + (nt * 16) * PADB + kt * 16, PADB);
                wmma::load_matrix_sync(bl, Wl + (nt * 16) * PADB + kt * 16, PADB);
                wmma::mma_sync(o[nt], ah, bh, o[nt]);
                wmma::mma_sync(o[nt], ah, bl, o[nt]);
                wmma::mma_sync(o[nt], al, bh, o[nt]);
            }
        }
    }

    float* Yb = Y + (size_t)hI * NTOK * 64;
    #pragma unroll
    for (int nt = 0; nt < 4; nt++)
        wmma::store_matrix_sync(Yb + (size_t)(n0 + wid * 16) * 64 + nt * 16,
                                o[nt], 64, wmma::mem_row_major);
}

// ---------------------------------------------------------------------------
// lambda[h]
// ---------------------------------------------------------------------------
__global__ void lam_kernel(const float* __restrict__ lq1, const float* __restrict__ lk1,
                           const float* __restrict__ lq2, const float* __restrict__ lk2)
{
    const int h = threadIdx.x >> 5, lane = threadIdx.x & 31;
    float p1 = lq1[h * DH + lane] * lk1[h * DH + lane];
    float p2 = lq2[h * DH + lane] * lk2[h * DH + lane];
    #pragma unroll
    for (int off = 16; off; off >>= 1) {
        p1 += __shfl_xor_sync(0xffffffffu, p1, off);
        p2 += __shfl_xor_sync(0xffffffffu, p2, off);
    }
    if (lane == 0) g_lam[h] = expf(p1) - expf(p2) + 0.8f;
}

// ---------------------------------------------------------------------------
// Tensor-core flash attention v4: BM=64 x BN=64, 128 threads, 4 warps.
// QK^T: bf16 hi/lo split; PV: tf32 pre-rounded (R10 tensor work — unchanged,
// NO ones-MMA). NEW vs R10: the entire exp/mask/l/epilogue machinery is
// WARP-LOCAL (each warp owns its 16-row S strip; PV reads only that strip):
//  - off-diag tiles: exp+tf32-round in registers, single P store, l summed
//    from the warp's own strip (same values, same order as R10 -> identical
//    numerics), __syncwarp only.
//  - diagonal tile: smem mask+exp pass on own rows, __syncwarp only.
//  - per-tile block syncs: 4 -> 2 (staging only). Epilogue warp-local.
// Pair folding: qb = bx and 35-bx. grid (18, 16), 56.5KB smem, 3 CTAs/SM.
// ---------------------------------------------------------------------------
__global__ __launch_bounds__(128) void attn_tc_kernel()
{
    extern __shared__ float sm[];
    __nv_bfloat16* Qhi = (__nv_bfloat16*)sm;         // [64][PADB]
    __nv_bfloat16* Qlo = Qhi + 64 * PADB;            // [64][PADB]
    __nv_bfloat16* Khi = Qlo + 64 * PADB;            // [64][PADB]
    __nv_bfloat16* Klo = Khi + 64 * PADB;            // [64][PADB]
    float* Vs = (float*)(Klo + 64 * PADB);           // [64][PADS] tf32-rounded
    float* Ss = Vs + 64 * PADS;                      // [64][PADS] S / P / O
    float* Ls = Ss + 64 * PADS;                      // [2][64]

    const int vh   = blockIdx.y;
    const int h    = vh >> 1;
    const int half = vh & 1;

    const float* __restrict__ Qp = g_q + (size_t)h * NTOK * 64 + half * DH;
    const float* __restrict__ Kp = g_k + (size_t)h * NTOK * 64 + half * DH;
    const float* __restrict__ Vp = g_v + (size_t)h * NTOK * 64;
    float* __restrict__ Op       = g_o + (size_t)vh * NTOK * 64;

    const int tid  = threadIdx.x;
    const int wid  = tid >> 5;             // 0..3, owns q-rows wid*16..+15
    const int lane = tid & 31;
    const int rloc = lane & 15;            // row within own strip
    const int r    = wid * 16 + rloc;      // row within 64-row block
    const int co   = (lane >> 4) * 32;     // column half (0 or 32)

    const float scale = 0.17677669529663687f;  // 1/sqrt(32)

    #pragma unroll 1
    for (int pass = 0; pass < 2; pass++) {
        const int qb = (pass == 0) ? (int)blockIdx.x : 35 - (int)blockIdx.x;
        const int n0 = qb * 64;

        __syncthreads();   // previous pass fully done with smem

        // Stage Q (scaled) split into bf16 hi/lo: 64 x 32
        #pragma unroll
        for (int i = 0; i < 16; i++) {
            const int idx = tid + i * 128;
            const int rr = idx >> 5, d = idx & 31;
            const float f = Qp[(size_t)(n0 + rr) * 64 + d] * scale;
            bf16_split(f, Qhi[rr * PADB + d], Qlo[rr * PADB + d]);
        }
        __syncthreads();

        // Per-warp Q fragments (row-major, k16), loaded once per pass
        HFragA qh[2], ql[2];
        #pragma unroll
        for (int kt = 0; kt < 2; kt++) {
            wmma::load_matrix_sync(qh[kt], Qhi + (wid * 16) * PADB + kt * 16, PADB);
            wmma::load_matrix_sync(ql[kt], Qlo + (wid * 16) * PADB + kt * 16, PADB);
        }

        FragC o_acc[4];
        #pragma unroll
        for (int nt = 0; nt < 4; nt++) wmma::fill_fragment(o_acc[nt], 0.0f);
        float lrow = 0.0f;

        const int kb_max = qb;
        for (int kb = 0; kb <= kb_max; kb++) {
            const int k0 = kb << 6;
            __syncthreads();   // previous tile's MMAs done reading Khi/Klo/Vs

            // Stage K 64x32, split bf16 hi/lo
            #pragma unroll
            for (int i = 0; i < 16; i++) {
                const int idx = tid + i * 128;
                const int rr = idx >> 5, d = idx & 31;
                bf16_split(Kp[(size_t)(k0 + rr) * 64 + d],
                           Khi[rr * PADB + d], Klo[rr * PADB + d]);
            }
            // Stage V 64x64, pre-rounded to tf32
            #pragma unroll
            for (int i = 0; i < 8; i++) {
                const int idx = tid + i * 128;
                const int rr = idx >> 4, c4 = (idx & 15) * 4;
                float4 f = *(const float4*)&Vp[(size_t)(k0 + rr) * 64 + c4];
                f.x = wmma::__float_to_tf32(f.x);
                f.y = wmma::__float_to_tf32(f.y);
                f.z = wmma::__float_to_tf32(f.z);
                f.w = wmma::__float_to_tf32(f.w);
                *(float4*)&Vs[rr * PADS + c4] = f;
            }
            __syncthreads();

            // S = Q K^T via bf16 split: qh*kh + qh*kl + ql*kh
            HFragC s_acc[4];
            #pragma unroll
            for (int nt = 0; nt < 4; nt++) wmma::fill_fragment(s_acc[nt], 0.0f);
            #pragma unroll
            for (int kt = 0; kt < 2; kt++) {
                #pragma unroll
                for (int nt = 0; nt < 4; nt++) {
                    HFragBc kh, kl;
                    wmma::load_matrix_sync(kh, Khi + (nt * 16) * PADB + kt * 16, PADB);
                    wmma::load_matrix_sync(kl, Klo + (nt * 16) * PADB + kt * 16, PADB);
                    wmma::mma_sync(s_acc[nt], qh[kt], kh, s_acc[nt]);
                    wmma::mma_sync(s_acc[nt], qh[kt], kl, s_acc[nt]);
                    wmma::mma_sync(s_acc[nt], ql[kt], kh, s_acc[nt]);
                }
            }

            if (kb != kb_max) {
                // Off-diagonal: exp + tf32-round in registers (all entries
                // valid), store P once into this warp's OWN strip.
                #pragma unroll
                for (int nt = 0; nt < 4; nt++) {
                    #pragma unroll
                    for (int i = 0; i < 8; i++)
                        s_acc[nt].x[i] = wmma::__float_to_tf32(__expf(s_acc[nt].x[i]));
                    wmma::store_matrix_sync(Ss + (wid * 16) * PADS + nt * 16,
                                            s_acc[nt], PADS, wmma::mem_row_major);
                }
                __syncwarp();
                // l from own strip (same values & order as the R10 pass)
                {
                    const float* row = Ss + r * PADS + co;
                    #pragma unroll
                    for (int i = 0; i < 8; i++) {
                        float4 f = *(const float4*)&row[i * 4];
                        lrow += (f.x + f.y) + (f.z + f.w);
                    }
                }
            } else {
                // Diagonal: store raw S, warp-local mask+exp on own rows
                #pragma unroll
                for (int nt = 0; nt < 4; nt++)
                    wmma::store_matrix_sync(Ss + (wid * 16) * PADS + nt * 16,
                                            s_acc[nt], PADS, wmma::mem_row_major);
                __syncwarp();
                {
                    float* row = Ss + r * PADS + co;
                    const int lim = n0 + r - k0 - co;   // valid while col <= lim
                    #pragma unroll
                    for (int i = 0; i < 8; i++) {
                        float4 f = *(float4*)&row[i * 4];
                        const int c = i * 4;
                        f.x = (c + 0 <= lim) ? wmma::__float_to_tf32(__expf(f.x)) : 0.0f;
                        f.y = (c + 1 <= lim) ? wmma::__float_to_tf32(__expf(f.y)) : 0.0f;
                        f.z = (c + 2 <= lim) ? wmma::__float_to_tf32(__expf(f.z)) : 0.0f;
                        f.w = (c + 3 <= lim) ? wmma::__float_to_tf32(__expf(f.w)) : 0.0f;
                        lrow += (f.x + f.y) + (f.z + f.w);
                        *(float4*)&row[i * 4] = f;
                    }
                }
                __syncwarp();
            }

            // O += P @ V (tf32, pure mma; P in own strip, V block-shared)
            #pragma unroll
            for (int kt = 0; kt < 8; kt++) {
                FragA a;
                wmma::load_matrix_sync(a, Ss + (wid * 16) * PADS + kt * 8, PADS);
                #pragma unroll
                for (int nt = 0; nt < 4; nt++) {
                    FragBr vb;
                    wmma::load_matrix_sync(vb, Vs + (kt * 8) * PADS + nt * 16, PADS);
                    wmma::mma_sync(o_acc[nt], a, vb, o_acc[nt]);
                }
            }
        }

        // Epilogue (warp-local): O frags -> own strip, combine l halves,
        // normalize, store
        #pragma unroll
        for (int nt = 0; nt < 4; nt++)
            wmma::store_matrix_sync(Ss + (wid * 16) * PADS + nt * 16, o_acc[nt],
                                    PADS, wmma::mem_row_major);
        Ls[(lane >> 4) * 64 + r] = lrow;
        __syncwarp();
        {
            const float inv = 1.0f / (Ls[r] + Ls[64 + r]);
            const float* row = Ss + r * PADS + co;
            float* dst = Op + (size_t)(n0 + r) * 64 + co;
            #pragma unroll
            for (int i = 0; i < 8; i++) {
                float4 f = *(const float4*)&row[i * 4];
                f.x *= inv; f.y *= inv; f.z *= inv; f.w *= inv;
                *(float4*)&dst[i * 4] = f;
            }
        }
    }
}

// ---------------------------------------------------------------------------
// Combine halves + RMS norm
// ---------------------------------------------------------------------------
__global__ __launch_bounds__(256) void combine_kernel(const float* __restrict__ rms_scale)
{
    const int n = blockIdx.x;
    const int h = threadIdx.x >> 5, lane = threadIdx.x & 31;
    const float lam = g_lam[h];

    const float* o1 = g_o + ((size_t)(2 * h) * NTOK + n) * 64;
    const float* o2 = g_o + ((size_t)(2 * h + 1) * NTOK + n) * 64;

    const float a = o1[lane]      - lam * o2[lane];
    const float b = o1[lane + 32] - lam * o2[lane + 32];

    float ss = a * a + b * b;
    #pragma unroll
    for (int off = 16; off; off >>= 1)
        ss += __shfl_xor_sync(0xffffffffu, ss, off);

    const float inv = rsqrtf(ss * (1.0f / 64.0f) + 1e-5f) * 0.2f;

    float* out = g_oc + (size_t)n * EDIM + h * 64;
    out[lane]      = a * inv * rms_scale[lane];
    out[lane + 32] = b * inv * rms_scale[lane + 32];
}

// ---------------------------------------------------------------------------
// Output projection, bf16 hi/lo-split 3-term wmma (R10 winner — unchanged).
// grid (36, 4), 128 threads.
// ---------------------------------------------------------------------------
__global__ __launch_bounds__(128) void out_tc_kernel(
    const float* __restrict__ Wo, float* __restrict__ out)
{
    __shared__ __nv_bfloat16 Ah[64 * PADB], Al[64 * PADB];  // Wo [c][e], e contiguous
    __shared__ __nv_bfloat16 Bh[64 * PADB], Bl[64 * PADB];  // oc [n][e], e contiguous

    const int tid = threadIdx.x;
    const int wid = tid >> 5;
    const int n0 = blockIdx.x * 64, c0 = blockIdx.y * 64;

    HFragC o[4];
    #pragma unroll
    for (int nt = 0; nt < 4; nt++) wmma::fill_fragment(o[nt], 0.0f);

    for (int e0 = 0; e0 < EDIM; e0 += 32) {
        __syncthreads();
        #pragma unroll
        for (int i = 0; i < 16; i++) {
            const int idx = tid + i * 128;
            const int cc = idx >> 5, el = idx & 31;
            bf16_split(Wo[(size_t)(c0 + cc) * EDIM + e0 + el],
                       Ah[cc * PADB + el], Al[cc * PADB + el]);
        }
        #pragma unroll
        for (int i = 0; i < 16; i++) {
            const int idx = tid + i * 128;
            const int nn = idx >> 5, el = idx & 31;
            bf16_split(g_oc[(size_t)(n0 + nn) * EDIM + e0 + el],
                       Bh[nn * PADB + el], Bl[nn * PADB + el]);
        }
        __syncthreads();

        #pragma unroll
        for (int kt = 0; kt < 2; kt++) {
            HFragA ah, al;   // (c, e) row-major
            wmma::load_matrix_sync(ah, Ah + (wid * 16) * PADB + kt * 16, PADB);
            wmma::load_matrix_sync(al, Al + (wid * 16) * PADB + kt * 16, PADB);
            #pragma unroll
            for (int nt = 0; nt < 4; nt++) {
                HFragBc bh, bl;  // (e, n) col-major view of oc[n][e]
                wmma::load_matrix_sync(bh, Bh + (nt * 16) * PADB + kt * 16, PADB);
                wmma::load_matrix_sync(bl, Bl + (nt * 16) * PADB + kt * 16, PADB);
                wmma::mma_sync(o[nt], ah, bh, o[nt]);
                wmma::mma_sync(o[nt], ah, bl, o[nt]);
                wmma::mma_sync(o[nt], al, bh, o[nt]);
            }
        }
    }

    #pragma unroll
    for (int nt = 0; nt < 4; nt++)
        wmma::store_matrix_sync(out + (size_t)(c0 + wid * 16) * NTOK + n0 + nt * 16,
                                o[nt], NTOK, wmma::mem_row_major);
}

// ---------------------------------------------------------------------------
// Launch
// ---------------------------------------------------------------------------
extern "C" void kernel_launch(void* const* d_in, const int* in_sizes, int n_in,
                              void* d_out, int out_size)
{
    const float* X   = (const float*)d_in[0];
    const float* Wq  = (const float*)d_in[1];
    const float* Wk  = (const float*)d_in[2];
    const float* Wv  = (const float*)d_in[3];
    const float* Wo  = (const float*)d_in[4];
    const float* lq1 = (const float*)d_in[5];
    const float* lk1 = (const float*)d_in[6];
    const float* lq2 = (const float*)d_in[7];
    const float* lk2 = (const float*)d_in[8];
    const float* rs  = (const float*)d_in[9];
    float* out = (float*)d_out;

    static bool attr_set = false;
    if (!attr_set) {
        cudaFuncSetAttribute(attn_tc_kernel,
                             cudaFuncAttributeMaxDynamicSharedMemorySize,
                             ATTN_SMEM_BYTES);
        attr_set = true;
    }

    proj_tc_kernel<<<dim3(NTOK / 64, EDIM / 64, 3), 128>>>(X, Wq, Wk, Wv);
    lam_kernel<<<1, 256>>>(lq1, lk1, lq2, lk2);
    attn_tc_kernel<<<dim3(18, VHEADS), 128, ATTN_SMEM_BYTES>>>();
    combine_kernel<<<NTOK, 256>>>(rs);
    out_tc_kernel<<<dim3(NTOK / 64, CDIM / 64), 128>>>(Wo, out);
}

// round 14
// speedup vs baseline: 1.0571x; 1.0316x over previous
#include <cuda_runtime.h>
#include <cuda_bf16.h>
#include <mma.h>
#include <math.h>

using namespace nvcuda;

// Problem constants
#define NTOK   2304     // 48*48 tokens
#define CDIM   256      // d_model
#define EDIM   512      // 2*d_model
#define HEADS  8
#define VHEADS 16       // heads * 2 softmax halves
#define DH     32       // per-half head dim
#define DV     64       // value dim per head

#define PADB 40         // Q/K bf16 smem row pitch (elements)
#define PADS 72         // S/V fp32 smem row pitch (floats)
// attn dynamic smem bytes:
//   Qhi/Qlo/Khi/Klo 4*(64*40*2) + Vs/Ss 2*(64*72*4) + Ls 128*4
#define ATTN_SMEM_BYTES (4*64*PADB*2 + 2*64*PADS*4 + 128*4)  // 56.5 KB -> 3 CTAs/SM

// ---------------------------------------------------------------------------
// Scratch (device globals)
// Pre-converted attention operands (written once by proj, read many times):
//   g_qhi/g_qlo : bf16 hi/lo of Q*scale   [(h*NTOK + n)*64 + d]
//   g_khi/g_klo : bf16 hi/lo of K         [(h*NTOK + n)*64 + d]
//   g_v         : tf32-rounded fp32 V     [(h*NTOK + n)*64 + d]
// ---------------------------------------------------------------------------
__device__ __nv_bfloat16 g_qhi[HEADS * NTOK * 64];
__device__ __nv_bfloat16 g_qlo[HEADS * NTOK * 64];
__device__ __nv_bfloat16 g_khi[HEADS * NTOK * 64];
__device__ __nv_bfloat16 g_klo[HEADS * NTOK * 64];
__device__ float g_v[HEADS * NTOK * 64];
__device__ float g_o[VHEADS * NTOK * 64];
__device__ float g_oc[NTOK * EDIM];
__device__ float g_lam[HEADS];

// tf32 fragments (PV path)
typedef wmma::fragment<wmma::matrix_a, 16, 16, 8, wmma::precision::tf32, wmma::row_major> FragA;
typedef wmma::fragment<wmma::matrix_b, 16, 16, 8, wmma::precision::tf32, wmma::row_major> FragBr;
typedef wmma::fragment<wmma::accumulator, 16, 16, 8, float> FragC;

// bf16 fragments
typedef wmma::fragment<wmma::matrix_a, 16, 16, 16, __nv_bfloat16, wmma::row_major> HFragA;
typedef wmma::fragment<wmma::matrix_a, 16, 16, 16, __nv_bfloat16, wmma::col_major> HFragAc;
typedef wmma::fragment<wmma::matrix_b, 16, 16, 16, __nv_bfloat16, wmma::col_major> HFragBc;
typedef wmma::fragment<wmma::accumulator, 16, 16, 16, float> HFragC;

__device__ __forceinline__ void bf16_split(float f, __nv_bfloat16& hi, __nv_bfloat16& lo)
{
    hi = __float2bfloat16_rn(f);
    lo = __float2bfloat16_rn(f - __bfloat162float(hi));
}

// ---------------------------------------------------------------------------
// QKV projection, bf16 hi/lo-split 3-term wmma (R10 mainloop) with a
// converting epilogue: Q (pre-scaled) and K written as bf16 hi/lo arrays,
// V written tf32-rounded — so attention staging is pure copy.
// Y[n][e] = sum_c X[c*NTOK+n] * W[e*256+c].  grid (36, 8, 3), 128 threads.
// ---------------------------------------------------------------------------
__global__ __launch_bounds__(128) void proj_tc_kernel(
    const float* __restrict__ X,
    const float* __restrict__ Wq,
    const float* __restrict__ Wk,
    const float* __restrict__ Wv)
{
    const int sel = blockIdx.z;
    const float* __restrict__ W = (sel == 0) ? Wq : (sel == 1) ? Wk : Wv;

    __shared__ __nv_bfloat16 Xh[32 * 72], Xl[32 * 72];     // [c][n], n contiguous
    __shared__ __nv_bfloat16 Wh[64 * PADB], Wl[64 * PADB]; // [e][c], c contiguous
    __shared__ float Sout[64 * 68];                        // result staging

    const int tid = threadIdx.x;
    const int wid = tid >> 5;
    const int n0 = blockIdx.x * 64;
    const int hI = blockIdx.y;

    HFragC o[4];
    #pragma unroll
    for (int nt = 0; nt < 4; nt++) wmma::fill_fragment(o[nt], 0.0f);

    for (int c0 = 0; c0 < CDIM; c0 += 32) {
        __syncthreads();
        #pragma unroll
        for (int i = 0; i < 16; i++) {
            const int idx = tid + i * 128;
            const int c = idx >> 6, nl = idx & 63;
            bf16_split(X[(size_t)(c0 + c) * NTOK + n0 + nl],
                       Xh[c * 72 + nl], Xl[c * 72 + nl]);
        }
        #pragma unroll
        for (int i = 0; i < 16; i++) {
            const int idx = tid + i * 128;
            const int e = idx >> 5, cl = idx & 31;
            bf16_split(W[(size_t)(hI * 64 + e) * CDIM + c0 + cl],
                       Wh[e * PADB + cl], Wl[e * PADB + cl]);
        }
        __syncthreads();

        #pragma unroll
        for (int kt = 0; kt < 2; kt++) {
            HFragAc ah, al;
            wmma::load_matrix_sync(ah, Xh + (kt * 16) * 72 + wid * 16, 72);
            wmma::load_matrix_sync(al, Xl + (kt * 16) * 72 + wid * 16, 72);
            #pragma unroll
            for (int nt = 0; nt < 4; nt++) {
                HFragBc bh, bl;
                wmma::load_matrix_sync(bh, Wh + (nt * 16) * PADB + kt * 16, PADB);
                wmma::load_matrix_sync(bl, Wl + (nt * 16) * PADB + kt * 16, PADB);
                wmma::mma_sync(o[nt], ah, bh, o[nt]);
                wmma::mma_sync(o[nt], ah, bl, o[nt]);
                wmma::mma_sync(o[nt], al, bh, o[nt]);
            }
        }
    }

    // Converting epilogue: frags -> Sout -> per-dtype global writes
    __syncthreads();
    #pragma unroll
    for (int nt = 0; nt < 4; nt++)
        wmma::store_matrix_sync(Sout + (wid * 16) * 68 + nt * 16, o[nt],
                                68, wmma::mem_row_major);
    __syncthreads();

    const size_t base = (size_t)hI * NTOK * 64 + (size_t)n0 * 64;
    const float scale = 0.17677669529663687f;  // 1/sqrt(32), folded into Q
    #pragma unroll
    for (int i = 0; i < 32; i++) {
        const int idx = tid + i * 128;              // 0..4095
        const int rr = idx >> 6, d = idx & 63;
        const float f = Sout[rr * 68 + d];
        const size_t gi = base + (size_t)rr * 64 + d;
        if (sel == 2) {
            g_v[gi] = wmma::__float_to_tf32(f);
        } else if (sel == 0) {
            bf16_split(f * scale, g_qhi[gi], g_qlo[gi]);
        } else {
            bf16_split(f, g_khi[gi], g_klo[gi]);
        }
    }
}

// ---------------------------------------------------------------------------
// lambda[h]
// ---------------------------------------------------------------------------
__global__ void lam_kernel(const float* __restrict__ lq1, const float* __restrict__ lk1,
                           const float* __restrict__ lq2, const float* __restrict__ lk2)
{
    const int h = threadIdx.x >> 5, lane = threadIdx.x & 31;
    float p1 = lq1[h * DH + lane] * lk1[h * DH + lane];
    float p2 = lq2[h * DH + lane] * lk2[h * DH + lane];
    #pragma unroll
    for (int off = 16; off; off >>= 1) {
        p1 += __shfl_xor_sync(0xffffffffu, p1, off);
        p2 += __shfl_xor_sync(0xffffffffu, p2, off);
    }
    if (lane == 0) g_lam[h] = expf(p1) - expf(p2) + 0.8f;
}

// ---------------------------------------------------------------------------
// Tensor-core flash attention — R10 structure EXACTLY (proven 237.6us),
// except all staging is now pure vector copy (operands pre-converted in
// global by proj): zero conversion ALU in the mainloop, same bytes, same
// smem layout, same sync structure, bit-identical operand values.
// Pair folding: qb = bx and 35-bx. grid (18, 16), 56.5KB smem, 3 CTAs/SM.
// ---------------------------------------------------------------------------
__global__ __launch_bounds__(128) void attn_tc_kernel()
{
    extern __shared__ float sm[];
    __nv_bfloat16* Qhi = (__nv_bfloat16*)sm;         // [64][PADB]
    __nv_bfloat16* Qlo = Qhi + 64 * PADB;            // [64][PADB]
    __nv_bfloat16* Khi = Qlo + 64 * PADB;            // [64][PADB]
    __nv_bfloat16* Klo = Khi + 64 * PADB;            // [64][PADB]
    float* Vs = (float*)(Klo + 64 * PADB);           // [64][PADS] tf32-rounded
    float* Ss = Vs + 64 * PADS;                      // [64][PADS] S / P / O
    float* Ls = Ss + 64 * PADS;                      // [2][64]

    const int vh   = blockIdx.y;
    const int h    = vh >> 1;
    const int half = vh & 1;

    const size_t hb = (size_t)h * NTOK * 64 + half * DH;   // base offset for Q/K
    const __nv_bfloat16* __restrict__ Gqhi = g_qhi + hb;
    const __nv_bfloat16* __restrict__ Gqlo = g_qlo + hb;
    const __nv_bfloat16* __restrict__ Gkhi = g_khi + hb;
    const __nv_bfloat16* __restrict__ Gklo = g_klo + hb;
    const float* __restrict__ Vp = g_v + (size_t)h * NTOK * 64;
    float* __restrict__ Op       = g_o + (size_t)vh * NTOK * 64;

    const int tid = threadIdx.x;
    const int wid = tid >> 5;              // 0..3, 16-row q strip

    #pragma unroll 1
    for (int pass = 0; pass < 2; pass++) {
        const int qb = (pass == 0) ? (int)blockIdx.x : 35 - (int)blockIdx.x;
        const int n0 = qb * 64;

        __syncthreads();   // previous pass fully done with smem

        // Stage Q hi/lo: pure uint4 copies (8 bf16 each), 2 per thread per array
        #pragma unroll
        for (int i = 0; i < 2; i++) {
            const int idx = tid + i * 128;           // 0..255
            const int rr = idx >> 2, c8 = (idx & 3) * 8;
            *(uint4*)&Qhi[rr * PADB + c8] =
                *(const uint4*)&Gqhi[(size_t)(n0 + rr) * 64 + c8];
            *(uint4*)&Qlo[rr * PADB + c8] =
                *(const uint4*)&Gqlo[(size_t)(n0 + rr) * 64 + c8];
        }
        __syncthreads();

        // Per-warp Q fragments (row-major, k16), loaded once per pass
        HFragA qh[2], ql[2];
        #pragma unroll
        for (int kt = 0; kt < 2; kt++) {
            wmma::load_matrix_sync(qh[kt], Qhi + (wid * 16) * PADB + kt * 16, PADB);
            wmma::load_matrix_sync(ql[kt], Qlo + (wid * 16) * PADB + kt * 16, PADB);
        }

        FragC o_acc[4];
        #pragma unroll
        for (int nt = 0; nt < 4; nt++) wmma::fill_fragment(o_acc[nt], 0.0f);
        float lrow = 0.0f;

        const int kb_max = qb;
        for (int kb = 0; kb <= kb_max; kb++) {
            const int k0 = kb << 6;
            __syncthreads();   // previous tile's MMAs done reading Khi/Klo/Vs

            // Stage K hi/lo: pure uint4 copies
            #pragma unroll
            for (int i = 0; i < 2; i++) {
                const int idx = tid + i * 128;
                const int rr = idx >> 2, c8 = (idx & 3) * 8;
                *(uint4*)&Khi[rr * PADB + c8] =
                    *(const uint4*)&Gkhi[(size_t)(k0 + rr) * 64 + c8];
                *(uint4*)&Klo[rr * PADB + c8] =
                    *(const uint4*)&Gklo[(size_t)(k0 + rr) * 64 + c8];
            }
            // Stage V: pure float4 copies (pre-rounded in global)
            #pragma unroll
            for (int i = 0; i < 8; i++) {
                const int idx = tid + i * 128;
                const int rr = idx >> 4, c4 = (idx & 15) * 4;
                *(float4*)&Vs[rr * PADS + c4] =
                    *(const float4*)&Vp[(size_t)(k0 + rr) * 64 + c4];
            }
            __syncthreads();

            // S = Q K^T via bf16 split: qh*kh + qh*kl + ql*kh
            HFragC s_acc[4];
            #pragma unroll
            for (int nt = 0; nt < 4; nt++) wmma::fill_fragment(s_acc[nt], 0.0f);
            #pragma unroll
            for (int kt = 0; kt < 2; kt++) {
                #pragma unroll
                for (int nt = 0; nt < 4; nt++) {
                    HFragBc kh, kl;
                    wmma::load_matrix_sync(kh, Khi + (nt * 16) * PADB + kt * 16, PADB);
                    wmma::load_matrix_sync(kl, Klo + (nt * 16) * PADB + kt * 16, PADB);
                    wmma::mma_sync(s_acc[nt], qh[kt], kh, s_acc[nt]);
                    wmma::mma_sync(s_acc[nt], qh[kt], kl, s_acc[nt]);
                    wmma::mma_sync(s_acc[nt], ql[kt], kh, s_acc[nt]);
                }
            }
            #pragma unroll
            for (int nt = 0; nt < 4; nt++)
                wmma::store_matrix_sync(Ss + (wid * 16) * PADS + nt * 16, s_acc[nt],
                                        PADS, wmma::mem_row_major);
            __syncthreads();

            // exp (+causal mask on diagonal), write tf32-rounded P, row sums
            {
                const int r  = tid & 63;
                const int co = (tid >> 6) * 32;
                float* row = Ss + r * PADS + co;
                if (kb == kb_max) {
                    const int lim = n0 + r - k0 - co;   // valid while col <= lim
                    #pragma unroll
                    for (int i = 0; i < 8; i++) {
                        float4 f = *(float4*)&row[i * 4];
                        const int c = i * 4;
                        f.x = (c + 0 <= lim) ? wmma::__float_to_tf32(__expf(f.x)) : 0.0f;
                        f.y = (c + 1 <= lim) ? wmma::__float_to_tf32(__expf(f.y)) : 0.0f;
                        f.z = (c + 2 <= lim) ? wmma::__float_to_tf32(__expf(f.z)) : 0.0f;
                        f.w = (c + 3 <= lim) ? wmma::__float_to_tf32(__expf(f.w)) : 0.0f;
                        lrow += (f.x + f.y) + (f.z + f.w);
                        *(float4*)&row[i * 4] = f;
                    }
                } else {
                    #pragma unroll
                    for (int i = 0; i < 8; i++) {
                        float4 f = *(float4*)&row[i * 4];
                        f.x = wmma::__float_to_tf32(__expf(f.x));
                        f.y = wmma::__float_to_tf32(__expf(f.y));
                        f.z = wmma::__float_to_tf32(__expf(f.z));
                        f.w = wmma::__float_to_tf32(__expf(f.w));
                        lrow += (f.x + f.y) + (f.z + f.w);
                        *(float4*)&row[i * 4] = f;
                    }
                }
            }
            __syncthreads();

            // O += P @ V (tf32, pure mma; operands pre-rounded in smem)
            #pragma unroll
            for (int kt = 0; kt < 8; kt++) {
                FragA a;
                wmma::load_matrix_sync(a, Ss + (wid * 16) * PADS + kt * 8, PADS);
                #pragma unroll
                for (int nt = 0; nt < 4; nt++) {
                    FragBr vb;
                    wmma::load_matrix_sync(vb, Vs + (kt * 8) * PADS + nt * 16, PADS);
                    wmma::mma_sync(o_acc[nt], a, vb, o_acc[nt]);
                }
            }
        }

        // Epilogue: O frags -> smem, combine l halves, normalize, store
        #pragma unroll
        for (int nt = 0; nt < 4; nt++)
            wmma::store_matrix_sync(Ss + (wid * 16) * PADS + nt * 16, o_acc[nt],
                                    PADS, wmma::mem_row_major);
        Ls[(tid >> 6) * 64 + (tid & 63)] = lrow;
        __syncthreads();
        {
            const int r  = tid & 63;
            const int co = (tid >> 6) * 32;
            const float inv = 1.0f / (Ls[r] + Ls[64 + r]);
            const float* row = Ss + r * PADS + co;
            float* dst = Op + (size_t)(n0 + r) * 64 + co;
            #pragma unroll
            for (int i = 0; i < 8; i++) {
                float4 f = *(const float4*)&row[i * 4];
                f.x *= inv; f.y *= inv; f.z *= inv; f.w *= inv;
                *(float4*)&dst[i * 4] = f;
            }
        }
    }
}

// ---------------------------------------------------------------------------
// Combine halves + RMS norm
// ---------------------------------------------------------------------------
__global__ __launch_bounds__(256) void combine_kernel(const float* __restrict__ rms_scale)
{
    const int n = blockIdx.x;
    const int h = threadIdx.x >> 5, lane = threadIdx.x & 31;
    const float lam = g_lam[h];

    const float* o1 = g_o + ((size_t)(2 * h) * NTOK + n) * 64;
    const float* o2 = g_o + ((size_t)(2 * h + 1) * NTOK + n) * 64;

    const float a = o1[lane]      - lam * o2[lane];
    const float b = o1[lane + 32] - lam * o2[lane + 32];

    float ss = a * a + b * b;
    #pragma unroll
    for (int off = 16; off; off >>= 1)
        ss += __shfl_xor_sync(0xffffffffu, ss, off);

    const float inv = rsqrtf(ss * (1.0f / 64.0f) + 1e-5f) * 0.2f;

    float* out = g_oc + (size_t)n * EDIM + h * 64;
    out[lane]      = a * inv * rms_scale[lane];
    out[lane + 32] = b * inv * rms_scale[lane + 32];
}

// ---------------------------------------------------------------------------
// Output projection, bf16 hi/lo-split 3-term wmma (R10 winner — unchanged).
// grid (36, 4), 128 threads.
// ---------------------------------------------------------------------------
__global__ __launch_bounds__(128) void out_tc_kernel(
    const float* __restrict__ Wo, float* __restrict__ out)
{
    __shared__ __nv_bfloat16 Ah[64 * PADB], Al[64 * PADB];  // Wo [c][e], e contiguous
    __shared__ __nv_bfloat16 Bh[64 * PADB], Bl[64 * PADB];  // oc [n][e], e contiguous

    const int tid = threadIdx.x;
    const int wid = tid >> 5;
    const int n0 = blockIdx.x * 64, c0 = blockIdx.y * 64;

    HFragC o[4];
    #pragma unroll
    for (int nt = 0; nt < 4; nt++) wmma::fill_fragment(o[nt], 0.0f);

    for (int e0 = 0; e0 < EDIM; e0 += 32) {
        __syncthreads();
        #pragma unroll
        for (int i = 0; i < 16; i++) {
            const int idx = tid + i * 128;
            const int cc = idx >> 5, el = idx & 31;
            bf16_split(Wo[(size_t)(c0 + cc) * EDIM + e0 + el],
                       Ah[cc * PADB + el], Al[cc * PADB + el]);
        }
        #pragma unroll
        for (int i = 0; i < 16; i++) {
            const int idx = tid + i * 128;
            const int nn = idx >> 5, el = idx & 31;
            bf16_split(g_oc[(size_t)(n0 + nn) * EDIM + e0 + el],
                       Bh[nn * PADB + el], Bl[nn * PADB + el]);
        }
        __syncthreads();

        #pragma unroll
        for (int kt = 0; kt < 2; kt++) {
            HFragA ah, al;   // (c, e) row-major
            wmma::load_matrix_sync(ah, Ah + (wid * 16) * PADB + kt * 16, PADB);
            wmma::load_matrix_sync(al, Al + (wid * 16) * PADB + kt * 16, PADB);
            #pragma unroll
            for (int nt = 0; nt < 4; nt++) {
                HFragBc bh, bl;  // (e, n) col-major view of oc[n][e]
                wmma::load_matrix_sync(bh, Bh + (nt * 16) * PADB + kt * 16, PADB);
                wmma::load_matrix_sync(bl, Bl + (nt * 16) * PADB + kt * 16, PADB);
                wmma::mma_sync(o[nt], ah, bh, o[nt]);
                wmma::mma_sync(o[nt], ah, bl, o[nt]);
                wmma::mma_sync(o[nt], al, bh, o[nt]);
            }
        }
    }

    #pragma unroll
    for (int nt = 0; nt < 4; nt++)
        wmma::store_matrix_sync(out + (size_t)(c0 + wid * 16) * NTOK + n0 + nt * 16,
                                o[nt], NTOK, wmma::mem_row_major);
}

// ---------------------------------------------------------------------------
// Launch
// ---------------------------------------------------------------------------
extern "C" void kernel_launch(void* const* d_in, const int* in_sizes, int n_in,
                              void* d_out, int out_size)
{
    const float* X   = (const float*)d_in[0];
    const float* Wq  = (const float*)d_in[1];
    const float* Wk  = (const float*)d_in[2];
    const float* Wv  = (const float*)d_in[3];
    const float* Wo  = (const float*)d_in[4];
    const float* lq1 = (const float*)d_in[5];
    const float* lk1 = (const float*)d_in[6];
    const float* lq2 = (const float*)d_in[7];
    const float* lk2 = (const float*)d_in[8];
    const float* rs  = (const float*)d_in[9];
    float* out = (float*)d_out;

    static bool attr_set = false;
    if (!attr_set) {
        cudaFuncSetAttribute(attn_tc_kernel,
                             cudaFuncAttributeMaxDynamicSharedMemorySize,
                             ATTN_SMEM_BYTES);
        attr_set = true;
    }

    proj_tc_kernel<<<dim3(NTOK / 64, EDIM / 64, 3), 128>>>(X, Wq, Wk, Wv);
    lam_kernel<<<1, 256>>>(lq1, lk1, lq2, lk2);
    attn_tc_kernel<<<dim3(18, VHEADS), 128, ATTN_SMEM_BYTES>>>();
    combine_kernel<<<NTOK, 256>>>(rs);
    out_tc_kernel<<<dim3(NTOK / 64, CDIM / 64), 128>>>(Wo, out);
}